// round 1
// baseline (speedup 1.0000x reference)
#include <cuda_runtime.h>

// Autoregressive RNN, HIDDEN=4096, STEPS=2048, input/output dim 1.
// Persistent kernel: 128 CTAs x 512 threads, one CTA per SM (smem-limited),
// each CTA owns 32 rows of W_hh. Weight residency per CTA (512KB of fp32):
//   - 5/16 in registers  (80 regs/lane)
//   - 6/16 in shared     (192KB)
//   - 5/16 streamed from L2 each step (addresses fixed -> L2 resident)
// Cross-step sync: monotonic u64 atomic grid barrier (graph-replay safe).
// Cross-CTA data (h ping-pong, y-partials ping-pong) read via __ldcg to
// bypass stale L1 lines.

#define HIDDEN 4096
#define STEPS  2048
#define NCTA   128
#define ROWS_PER_CTA 32
#define NTHREADS 512
#define K_R 5   // col-iterations cached in registers
#define K_S 6   // col-iterations cached in shared
#define K_G 5   // col-iterations streamed from global (L2)
// 16 iterations total x 32 cols = 512 cols per warp-slice; 8 slices = 4096.

__device__ unsigned long long g_barrier;     // zero-init, monotonic across replays
__device__ float g_h[2][HIDDEN];             // hidden state ping-pong
__device__ float g_party[2][NCTA];           // per-CTA partial of W_out . h

__global__ __launch_bounds__(NTHREADS, 1)
void rnn_persistent_kernel(const float* __restrict__ inputs,
                           const float* __restrict__ W_ih,
                           const float* __restrict__ W_hh,
                           const float* __restrict__ b_ih,
                           const float* __restrict__ b_hh,
                           const float* __restrict__ W_out,
                           const float* __restrict__ b_out,
                           float* __restrict__ out, int out_size)
{
    extern __shared__ float smem[];
    float* h_s    = smem;                                  // 4096 floats
    float* sw     = smem + HIDDEN;                         // 16*K_S*16*32 floats
    float* s_part = sw + 16 * K_S * 16 * 32;               // 32*8 floats
    float* s_x    = s_part + ROWS_PER_CTA * 8;             // 1 float (+pad)

    const int tid = threadIdx.x;
    const int w   = tid >> 5;          // warp 0..15
    const int l   = tid & 31;          // lane
    const int g   = w >> 3;            // row-group 0..1  (16 rows each)
    const int c   = w & 7;             // column slice 0..7 (512 cols each)
    const int cta = blockIdx.x;
    const int RB  = cta * ROWS_PER_CTA + g * 16;   // first global row of this warp
    const int c512 = c * 512;

    // ---- preload register-cached weights: W_hh[RB+j][c512 + i*32 + l] ----
    float wreg[K_R * 16];
    #pragma unroll
    for (int i = 0; i < K_R; i++)
        #pragma unroll
        for (int j = 0; j < 16; j++)
            wreg[i * 16 + j] = W_hh[(size_t)(RB + j) * HIDDEN + c512 + i * 32 + l];

    // ---- preload shared-cached weights (iterations K_R .. K_R+K_S-1) ----
    for (int i = 0; i < K_S; i++)
        for (int j = 0; j < 16; j++)
            sw[((w * K_S + i) * 16 + j) * 32 + l] =
                W_hh[(size_t)(RB + j) * HIDDEN + c512 + (K_R + i) * 32 + l];

    // ---- per-row ("finisher") constants: warp 0, thread r owns row r ----
    float f_wih = 0.f, f_bsum = 0.f, f_wout = 0.f;
    if (tid < ROWS_PER_CTA) {
        int R  = cta * ROWS_PER_CTA + tid;
        f_wih  = W_ih[R];
        f_bsum = b_ih[R] + b_hh[R];
        f_wout = W_out[R];
    }
    const float bo = b_out[0];
    const bool has_hf = (out_size >= STEPS + HIDDEN);
    const float* wg_base = W_hh + (size_t)RB * HIDDEN + c512 + (K_R + K_S) * 32 + l;

    for (int t = 0; t < STEPS; ++t) {
        // ---- load h into shared; compute scalar input x ----
        if (t == 0) {
            for (int idx = tid; idx < HIDDEN; idx += NTHREADS) h_s[idx] = 0.f;
            if (tid == 0) s_x[0] = inputs[0];     // only inputs[0] is ever consumed
        } else {
            const float* hb = g_h[t & 1];
            for (int idx = tid; idx < HIDDEN; idx += NTHREADS)
                h_s[idx] = __ldcg(hb + idx);
            if (tid == 0) {
                const float* py = g_party[(t & 1) ^ 1];   // written at step t-1
                float y = bo;
                #pragma unroll 8
                for (int b2 = 0; b2 < NCTA; b2++) y += __ldcg(py + b2);
                s_x[0] = y;
                if (cta == 0) out[t - 1] = y;             // ys[t-1]
            }
        }
        __syncthreads();
        const float x = s_x[0];

        // ---- matvec partials: 16 rows x 512-col slice per warp ----
        float acc[16];
        #pragma unroll
        for (int j = 0; j < 16; j++) acc[j] = 0.f;

        // register-cached portion
        #pragma unroll
        for (int i = 0; i < K_R; i++) {
            float hv = h_s[c512 + i * 32 + l];
            #pragma unroll
            for (int j = 0; j < 16; j++) acc[j] = fmaf(wreg[i * 16 + j], hv, acc[j]);
        }
        // shared-cached portion
        #pragma unroll
        for (int i = 0; i < K_S; i++) {
            float hv = h_s[c512 + (K_R + i) * 32 + l];
            const float* wp = sw + ((w * K_S + i) * 16) * 32 + l;
            #pragma unroll
            for (int j = 0; j < 16; j++) acc[j] = fmaf(wp[j * 32], hv, acc[j]);
        }
        // streamed (L2-resident) portion
        #pragma unroll
        for (int i = 0; i < K_G; i++) {
            float hv = h_s[c512 + (K_R + K_S + i) * 32 + l];
            const float* wp = wg_base + i * 32;
            #pragma unroll
            for (int j = 0; j < 16; j++)
                acc[j] = fmaf(__ldg(wp + (size_t)j * HIDDEN), hv, acc[j]);
        }

        // ---- warp butterfly reduce each row partial; lane0 -> s_part ----
        #pragma unroll
        for (int j = 0; j < 16; j++) {
            float v = acc[j];
            v += __shfl_xor_sync(0xffffffffu, v, 16);
            v += __shfl_xor_sync(0xffffffffu, v, 8);
            v += __shfl_xor_sync(0xffffffffu, v, 4);
            v += __shfl_xor_sync(0xffffffffu, v, 2);
            v += __shfl_xor_sync(0xffffffffu, v, 1);
            if (l == 0) s_part[(g * 16 + j) * 8 + c] = v;
        }
        __syncthreads();

        // ---- finisher: combine 8 slice-partials, tanh, publish ----
        if (tid < ROWS_PER_CTA) {
            float dot = 0.f;
            #pragma unroll
            for (int k = 0; k < 8; k++) dot += s_part[tid * 8 + k];
            float pre  = fmaf(x, f_wih, f_bsum + dot);
            float hnew = tanhf(pre);
            g_h[(t + 1) & 1][cta * ROWS_PER_CTA + tid] = hnew;

            float pv = hnew * f_wout;                  // partial of W_out . h
            pv += __shfl_xor_sync(0xffffffffu, pv, 16);
            pv += __shfl_xor_sync(0xffffffffu, pv, 8);
            pv += __shfl_xor_sync(0xffffffffu, pv, 4);
            pv += __shfl_xor_sync(0xffffffffu, pv, 2);
            pv += __shfl_xor_sync(0xffffffffu, pv, 1);
            if (tid == 0) g_party[t & 1][cta] = pv;

            if (t == STEPS - 1 && has_hf)
                out[STEPS + cta * ROWS_PER_CTA + tid] = hnew;
            __threadfence();   // release hnew / party before barrier arrival
        }

        // ---- grid barrier (monotonic, graph-replay safe) ----
        __syncthreads();
        if (tid == 0) {
            unsigned long long old    = atomicAdd(&g_barrier, 1ULL);
            unsigned long long target = (old / NCTA + 1ULL) * NCTA;
            while (*((volatile unsigned long long*)&g_barrier) < target) { }
            __threadfence();
        }
        __syncthreads();
    }

    // final readout ys[2047] (party of step 2047 is in buffer (2047&1)=1)
    if (cta == 0 && tid == 0) {
        const float* py = g_party[(STEPS - 1) & 1];
        float y = bo;
        #pragma unroll 8
        for (int b2 = 0; b2 < NCTA; b2++) y += __ldcg(py + b2);
        out[STEPS - 1] = y;
    }
}

extern "C" void kernel_launch(void* const* d_in, const int* in_sizes, int n_in,
                              void* d_out, int out_size)
{
    const float* inputs = (const float*)d_in[0];
    const float* W_ih   = (const float*)d_in[1];
    const float* W_hh   = (const float*)d_in[2];
    const float* b_ih   = (const float*)d_in[3];
    const float* b_hh   = (const float*)d_in[4];
    const float* W_out  = (const float*)d_in[5];
    const float* b_out  = (const float*)d_in[6];
    float* out = (float*)d_out;

    // dynamic smem: h(4096) + sw(16*K_S*16*32) + part(256) + x(8 pad) floats
    const int smem_bytes = (HIDDEN + 16 * K_S * 16 * 32 + ROWS_PER_CTA * 8 + 8)
                           * (int)sizeof(float);
    cudaFuncSetAttribute(rnn_persistent_kernel,
                         cudaFuncAttributeMaxDynamicSharedMemorySize, smem_bytes);

    rnn_persistent_kernel<<<NCTA, NTHREADS, smem_bytes>>>(
        inputs, W_ih, W_hh, b_ih, b_hh, W_out, b_out, out, out_size);
}

// round 3
// speedup vs baseline: 1.0614x; 1.0614x over previous
#include <cuda_runtime.h>
#include <cstdint>

// Autoregressive RNN, HIDDEN=4096, STEPS=2048.
// 128 persistent CTAs x 512 threads, CTA owns 32 rows of W_hh.
// Weight tiers per CTA (512KB): 160KB regs, 192KB smem, 160KB streamed (L2-resident).
// Sync: per-CTA monotonic tag (no atomics). Poll warp (w15) scans all 128 tags
// with one uint4 load/lane (asm volatile -> cannot be hoisted), releases the CTA
// via a volatile smem epoch. Finisher warp (w0) gathers y-partials itself.

#define HIDDEN 4096
#define STEPS  2048
#define NCTA   128
#define ROWS   32
#define NTH    512
#define KR 5
#define KS 6
#define KG 5

__device__ unsigned int g_tag[NCTA];     // monotonic across graph replays
__device__ float g_h[2][HIDDEN];         // hidden state ping-pong
__device__ float g_party[2][NCTA];       // per-CTA partials of W_out . h

// Volatile .cg vector load: compiler may NOT hoist this out of a spin loop.
__device__ __forceinline__ uint4 ld_cg_v4_volatile(const uint4* p) {
    uint4 v;
    asm volatile("ld.global.cg.v4.b32 {%0,%1,%2,%3}, [%4];"
                 : "=r"(v.x), "=r"(v.y), "=r"(v.z), "=r"(v.w)
                 : "l"(p) : "memory");
    return v;
}

__global__ __launch_bounds__(NTH, 1)
void rnn_kernel(const float* __restrict__ inputs,
                const float* __restrict__ W_ih,
                const float* __restrict__ W_hh,
                const float* __restrict__ b_ih,
                const float* __restrict__ b_hh,
                const float* __restrict__ W_out,
                const float* __restrict__ b_out,
                float* __restrict__ out, int out_size)
{
    extern __shared__ float smem[];
    float* sw     = smem;                         // [16][KS][16][32] weights
    float* h_sw   = sw + 16 * KS * 16 * 32;       // [8][512] h slices
    float* s_part = h_sw + 8 * 512;               // [2][32][8] row partials
    volatile unsigned int* s_ready = (volatile unsigned int*)(s_part + 2 * 32 * 8);

    const int tid = threadIdx.x;
    const int w   = tid >> 5;
    const int l   = tid & 31;
    const int g   = w >> 3;        // 0/1: row half
    const int c   = w & 7;         // column slice 0..7
    const int cta = blockIdx.x;
    const int RB  = cta * ROWS + g * 16;
    const int c512 = c * 512;

    if (tid == 0) s_ready[0] = 0u;

    // Monotonic base: own slot; uniform across CTAs at every launch start.
    const unsigned int base = __ldcg(&g_tag[cta]);

    // ---- preload register tier ----
    float wreg[KR * 16];
    #pragma unroll
    for (int i = 0; i < KR; i++)
        #pragma unroll
        for (int j = 0; j < 16; j++)
            wreg[i * 16 + j] = W_hh[(size_t)(RB + j) * HIDDEN + c512 + i * 32 + l];

    // ---- preload shared tier: sw[w][i][j][l] ----
    for (int i = 0; i < KS; i++)
        for (int j = 0; j < 16; j++)
            sw[((w * KS + i) * 16 + j) * 32 + l] =
                W_hh[(size_t)(RB + j) * HIDDEN + c512 + (KR + i) * 32 + l];

    // zero h slices (h_{-1} = 0)
    for (int idx = tid; idx < 8 * 512; idx += NTH) h_sw[idx] = 0.f;

    float f_wih = 0.f, f_b = 0.f, f_wout = 0.f;
    if (w == 0) {
        int R  = cta * ROWS + l;
        f_wih  = W_ih[R];
        f_b    = b_ih[R] + b_hh[R];
        f_wout = W_out[R];
    }
    const float bo = b_out[0];
    const float x0 = inputs[0];
    const float* wg = W_hh + (size_t)RB * HIDDEN + c512 + (KR + KS) * 32 + l;

    __syncthreads();

    #pragma unroll 1
    for (int t = 0; t < STEPS; t++) {
        float x = x0;                      // meaningful only in warp 0

        if (t > 0) {
            const unsigned int tgt = base + (unsigned)t;
            if (w == 15) {
                // poll all 128 tags: one uint4 per lane, un-hoistable
                const uint4* tp = (const uint4*)g_tag;
                for (;;) {
                    uint4 v = ld_cg_v4_volatile(tp + l);
                    bool ok = (v.x >= tgt) & (v.y >= tgt) & (v.z >= tgt) & (v.w >= tgt);
                    if (__all_sync(0xffffffffu, ok)) break;
                    __nanosleep(40);
                }
                asm volatile("fence.acq_rel.gpu;" ::: "memory");
                __syncwarp();
                if (l == 0) s_ready[0] = (unsigned)t;
            } else {
                while (s_ready[0] < (unsigned)t) { }
                asm volatile("fence.acq_rel.gpu;" ::: "memory");
            }

            // finisher: gather y_{t-1} partials
            if (w == 0) {
                const float* py = g_party[(t - 1) & 1];
                float pv = __ldcg(py + l) + __ldcg(py + 32 + l)
                         + __ldcg(py + 64 + l) + __ldcg(py + 96 + l);
                pv += __shfl_xor_sync(0xffffffffu, pv, 16);
                pv += __shfl_xor_sync(0xffffffffu, pv, 8);
                pv += __shfl_xor_sync(0xffffffffu, pv, 4);
                pv += __shfl_xor_sync(0xffffffffu, pv, 2);
                pv += __shfl_xor_sync(0xffffffffu, pv, 1);
                x = bo + pv;
                if (cta == 0 && l == 0) out[t - 1] = x;   // ys[t-1]
            }

            // stage this pair's h slice: g=0 loads quarters 0,1; g=1 loads 2,3
            {
                const float4* hb4 = (const float4*)(g_h[(t - 1) & 1] + c512);
                float4* hs4 = (float4*)(h_sw + c512);
                int q0 = g * 2;
                float4 v0 = __ldcg(hb4 + q0 * 32 + l);
                float4 v1 = __ldcg(hb4 + (q0 + 1) * 32 + l);
                hs4[q0 * 32 + l] = v0;
                hs4[(q0 + 1) * 32 + l] = v1;
            }
        }
        // pair barrier: warps c and c+8 (64 threads), named barrier 1+c
        asm volatile("bar.sync %0, 64;" :: "r"(1 + c) : "memory");

        // ---- matvec: 16 rows x 512-col slice per warp ----
        float acc[16];
        #pragma unroll
        for (int j = 0; j < 16; j++) acc[j] = 0.f;

        #pragma unroll
        for (int i = 0; i < KR; i++) {
            float hv = h_sw[c512 + i * 32 + l];
            #pragma unroll
            for (int j = 0; j < 16; j++) acc[j] = fmaf(wreg[i * 16 + j], hv, acc[j]);
        }
        #pragma unroll
        for (int i = 0; i < KS; i++) {
            float hv = h_sw[c512 + (KR + i) * 32 + l];
            const float* wp = sw + ((w * KS + i) * 16) * 32 + l;
            #pragma unroll
            for (int j = 0; j < 16; j++) acc[j] = fmaf(wp[j * 32], hv, acc[j]);
        }
        #pragma unroll
        for (int i = 0; i < KG; i++) {
            float hv = h_sw[c512 + (KR + KS + i) * 32 + l];
            const float* wp = wg + i * 32;
            #pragma unroll
            for (int j = 0; j < 16; j++)
                acc[j] = fmaf(__ldg(wp + (size_t)j * HIDDEN), hv, acc[j]);
        }

        // warp reduce each row partial -> s_part[t&1]
        float* spb = s_part + (t & 1) * 256;
        #pragma unroll
        for (int j = 0; j < 16; j++) {
            float v = acc[j];
            v += __shfl_xor_sync(0xffffffffu, v, 16);
            v += __shfl_xor_sync(0xffffffffu, v, 8);
            v += __shfl_xor_sync(0xffffffffu, v, 4);
            v += __shfl_xor_sync(0xffffffffu, v, 2);
            v += __shfl_xor_sync(0xffffffffu, v, 1);
            if (l == 0) spb[(g * 16 + j) * 8 + c] = v;
        }
        __syncthreads();

        // ---- finisher: combine slices, tanh, publish, tag ----
        if (w == 0) {
            const float4* sp4 = (const float4*)(s_part + (t & 1) * 256 + l * 8);
            float4 a = sp4[0], b4 = sp4[1];
            float dot = ((a.x + a.y) + (a.z + a.w)) + ((b4.x + b4.y) + (b4.z + b4.w));
            float pre  = fmaf(x, f_wih, f_b + dot);
            float hnew = tanhf(pre);
            __stcg(&g_h[t & 1][cta * ROWS + l], hnew);

            float pv = hnew * f_wout;
            pv += __shfl_xor_sync(0xffffffffu, pv, 16);
            pv += __shfl_xor_sync(0xffffffffu, pv, 8);
            pv += __shfl_xor_sync(0xffffffffu, pv, 4);
            pv += __shfl_xor_sync(0xffffffffu, pv, 2);
            pv += __shfl_xor_sync(0xffffffffu, pv, 1);
            if (l == 0) __stcg(&g_party[t & 1][cta], pv);

            if (t == STEPS - 1 && out_size >= STEPS + HIDDEN)
                out[STEPS + cta * ROWS + l] = hnew;

            __syncwarp();
            asm volatile("fence.acq_rel.gpu;" ::: "memory");
            if (l == 0) __stcg(&g_tag[cta], base + (unsigned)t + 1u);
        }
    }

    // final readout ys[STEPS-1] by CTA 0 warp 0
    if (cta == 0 && w == 0) {
        const unsigned int tgt = base + (unsigned)STEPS;
        const uint4* tp = (const uint4*)g_tag;
        for (;;) {
            uint4 v = ld_cg_v4_volatile(tp + l);
            bool ok = (v.x >= tgt) & (v.y >= tgt) & (v.z >= tgt) & (v.w >= tgt);
            if (__all_sync(0xffffffffu, ok)) break;
            __nanosleep(40);
        }
        asm volatile("fence.acq_rel.gpu;" ::: "memory");
        const float* py = g_party[(STEPS - 1) & 1];
        float pv = __ldcg(py + l) + __ldcg(py + 32 + l)
                 + __ldcg(py + 64 + l) + __ldcg(py + 96 + l);
        pv += __shfl_xor_sync(0xffffffffu, pv, 16);
        pv += __shfl_xor_sync(0xffffffffu, pv, 8);
        pv += __shfl_xor_sync(0xffffffffu, pv, 4);
        pv += __shfl_xor_sync(0xffffffffu, pv, 2);
        pv += __shfl_xor_sync(0xffffffffu, pv, 1);
        if (l == 0) out[STEPS - 1] = bo + pv;
    }
}

extern "C" void kernel_launch(void* const* d_in, const int* in_sizes, int n_in,
                              void* d_out, int out_size)
{
    const float* inputs = (const float*)d_in[0];
    const float* W_ih   = (const float*)d_in[1];
    const float* W_hh   = (const float*)d_in[2];
    const float* b_ih   = (const float*)d_in[3];
    const float* b_hh   = (const float*)d_in[4];
    const float* W_out  = (const float*)d_in[5];
    const float* b_out  = (const float*)d_in[6];
    float* out = (float*)d_out;

    const int smem_bytes = (16 * KS * 16 * 32 + 8 * 512 + 2 * 32 * 8 + 8)
                           * (int)sizeof(float);
    cudaFuncSetAttribute(rnn_kernel,
                         cudaFuncAttributeMaxDynamicSharedMemorySize, smem_bytes);

    rnn_kernel<<<NCTA, NTH, smem_bytes>>>(
        inputs, W_ih, W_hh, b_ih, b_hh, W_out, b_out, out, out_size);
}

// round 4
// speedup vs baseline: 1.0625x; 1.0010x over previous
#include <cuda_runtime.h>
#include <cstdint>

// Autoregressive RNN, HIDDEN=4096, STEPS=2048.
// 128 persistent CTAs x 512 threads; CTA owns 32 rows of W_hh.
// Weight tiers per CTA (512KB): 128KB regs (KR=4), 192KB smem (KS=6),
// 192KB streamed from L2 (KG=6, software-pipelined, first chunk issued
// during the wait phase).
// Sync: per-CTA monotonic tag. Consumer side is fence-free (control-dependence
// ordering on .cg loads); producer (finisher warp) does one release fence.

#define HIDDEN 4096
#define STEPS  2048
#define NCTA   128
#define ROWS   32
#define NTH    512
#define KR 4
#define KS 6
#define KG 6

__device__ unsigned int g_tag[NCTA];     // monotonic across graph replays
__device__ float g_h[2][HIDDEN];         // hidden state ping-pong
__device__ float g_party[2][NCTA];       // per-CTA partials of W_out . h

__device__ __forceinline__ uint4 ld_cg_v4_volatile(const uint4* p) {
    uint4 v;
    asm volatile("ld.global.cg.v4.b32 {%0,%1,%2,%3}, [%4];"
                 : "=r"(v.x), "=r"(v.y), "=r"(v.z), "=r"(v.w)
                 : "l"(p) : "memory");
    return v;
}

__global__ __launch_bounds__(NTH, 1)
void rnn_kernel(const float* __restrict__ inputs,
                const float* __restrict__ W_ih,
                const float* __restrict__ W_hh,
                const float* __restrict__ b_ih,
                const float* __restrict__ b_hh,
                const float* __restrict__ W_out,
                const float* __restrict__ b_out,
                float* __restrict__ out, int out_size)
{
    extern __shared__ float smem[];
    float* sw     = smem;                         // [16][KS][16][32] weights
    float* h_sw   = sw + 16 * KS * 16 * 32;       // [8][512] h slices
    float* s_part = h_sw + 8 * 512;               // [2][32][8] row partials
    volatile unsigned int* s_ready = (volatile unsigned int*)(s_part + 2 * 32 * 8);

    const int tid = threadIdx.x;
    const int w   = tid >> 5;
    const int l   = tid & 31;
    const int g   = w >> 3;        // 0/1: row half
    const int c   = w & 7;         // column slice 0..7
    const int cta = blockIdx.x;
    const int RB  = cta * ROWS + g * 16;
    const int c512 = c * 512;

    if (tid == 0) s_ready[0] = 0u;

    const unsigned int base = __ldcg(&g_tag[cta]);

    // ---- register tier: i = 0..KR-1 ----
    float wreg[KR * 16];
    #pragma unroll
    for (int i = 0; i < KR; i++)
        #pragma unroll
        for (int j = 0; j < 16; j++)
            wreg[i * 16 + j] = W_hh[(size_t)(RB + j) * HIDDEN + c512 + i * 32 + l];

    // ---- shared tier: i = KR..KR+KS-1 ----
    for (int i = 0; i < KS; i++)
        for (int j = 0; j < 16; j++)
            sw[((w * KS + i) * 16 + j) * 32 + l] =
                W_hh[(size_t)(RB + j) * HIDDEN + c512 + (KR + i) * 32 + l];

    for (int idx = tid; idx < 8 * 512; idx += NTH) h_sw[idx] = 0.f;

    float f_wih = 0.f, f_b = 0.f, f_wout = 0.f;
    if (w == 0) {
        int R  = cta * ROWS + l;
        f_wih  = W_ih[R];
        f_b    = b_ih[R] + b_hh[R];
        f_wout = W_out[R];
    }
    const float bo = b_out[0];
    const float x0 = inputs[0];
    const float* wg = W_hh + (size_t)RB * HIDDEN + c512 + (KR + KS) * 32 + l;

    __syncthreads();

    #pragma unroll 1
    for (int t = 0; t < STEPS; t++) {
        float x = x0;                      // meaningful only in warp 0

        // prefetch streamed chunk i=0 — independent of h, lands during the wait
        float buf[16];
        #pragma unroll
        for (int j = 0; j < 16; j++) buf[j] = __ldcg(wg + (size_t)j * HIDDEN);

        if (t > 0) {
            const unsigned int tgt = base + (unsigned)t;
            if (w == 15) {
                const uint4* tp = (const uint4*)g_tag;
                for (;;) {
                    uint4 v = ld_cg_v4_volatile(tp + l);
                    bool ok = (v.x >= tgt) & (v.y >= tgt) & (v.z >= tgt) & (v.w >= tgt);
                    if (__all_sync(0xffffffffu, ok)) break;
                    __nanosleep(20);
                }
                __syncwarp();
                if (l == 0) s_ready[0] = (unsigned)t;
            } else {
                while (s_ready[0] < (unsigned)t) { }
            }
            asm volatile("" ::: "memory");   // compiler barrier only

            // finisher: gather y_{t-1} partials (consumed only after matvec)
            if (w == 0) {
                const float* py = g_party[(t - 1) & 1];
                float pv = __ldcg(py + l) + __ldcg(py + 32 + l)
                         + __ldcg(py + 64 + l) + __ldcg(py + 96 + l);
                pv += __shfl_xor_sync(0xffffffffu, pv, 16);
                pv += __shfl_xor_sync(0xffffffffu, pv, 8);
                pv += __shfl_xor_sync(0xffffffffu, pv, 4);
                pv += __shfl_xor_sync(0xffffffffu, pv, 2);
                pv += __shfl_xor_sync(0xffffffffu, pv, 1);
                x = bo + pv;
                if (cta == 0 && l == 0) out[t - 1] = x;   // ys[t-1]
            }

            // stage this pair's h slice: g=0 loads quarters 0,1; g=1 loads 2,3
            {
                const float4* hb4 = (const float4*)(g_h[(t - 1) & 1] + c512);
                float4* hs4 = (float4*)(h_sw + c512);
                int q0 = g * 2;
                float4 v0 = __ldcg(hb4 + q0 * 32 + l);
                float4 v1 = __ldcg(hb4 + (q0 + 1) * 32 + l);
                hs4[q0 * 32 + l] = v0;
                hs4[(q0 + 1) * 32 + l] = v1;
            }
        }
        // pair barrier: warps c and c+8 (64 threads)
        asm volatile("bar.sync %0, 64;" :: "r"(1 + c) : "memory");

        // ---- matvec: 16 rows x 512-col slice per warp ----
        float acc[16];
        #pragma unroll
        for (int j = 0; j < 16; j++) acc[j] = 0.f;

        // register tier
        #pragma unroll
        for (int i = 0; i < KR; i++) {
            float hv = h_sw[c512 + i * 32 + l];
            #pragma unroll
            for (int j = 0; j < 16; j++) acc[j] = fmaf(wreg[i * 16 + j], hv, acc[j]);
        }

        // streamed tier (pipelined) interleaved 1:1 with shared tier
        #pragma unroll
        for (int i = 0; i < KG; i++) {
            float hvg = h_sw[c512 + (KR + KS + i) * 32 + l];
            #pragma unroll
            for (int j = 0; j < 16; j++) acc[j] = fmaf(buf[j], hvg, acc[j]);
            if (i + 1 < KG) {
                const float* wp = wg + (i + 1) * 32;
                #pragma unroll
                for (int j = 0; j < 16; j++) buf[j] = __ldcg(wp + (size_t)j * HIDDEN);
            }
            // shared-tier iteration i
            float hvs = h_sw[c512 + (KR + i) * 32 + l];
            const float* sp = sw + ((w * KS + i) * 16) * 32 + l;
            #pragma unroll
            for (int j = 0; j < 16; j++) acc[j] = fmaf(sp[j * 32], hvs, acc[j]);
        }

        // warp reduce each row partial -> s_part[t&1]
        float* spb = s_part + (t & 1) * 256;
        #pragma unroll
        for (int j = 0; j < 16; j++) {
            float v = acc[j];
            v += __shfl_xor_sync(0xffffffffu, v, 16);
            v += __shfl_xor_sync(0xffffffffu, v, 8);
            v += __shfl_xor_sync(0xffffffffu, v, 4);
            v += __shfl_xor_sync(0xffffffffu, v, 2);
            v += __shfl_xor_sync(0xffffffffu, v, 1);
            if (l == 0) spb[(g * 16 + j) * 8 + c] = v;
        }
        __syncthreads();

        // ---- finisher: combine slices, tanh, publish, release, tag ----
        if (w == 0) {
            const float4* sp4 = (const float4*)(s_part + (t & 1) * 256 + l * 8);
            float4 a = sp4[0], b4 = sp4[1];
            float dot = ((a.x + a.y) + (a.z + a.w)) + ((b4.x + b4.y) + (b4.z + b4.w));
            float pre  = fmaf(x, f_wih, f_b + dot);
            float hnew = tanhf(pre);
            __stcg(&g_h[t & 1][cta * ROWS + l], hnew);

            float pv = hnew * f_wout;
            pv += __shfl_xor_sync(0xffffffffu, pv, 16);
            pv += __shfl_xor_sync(0xffffffffu, pv, 8);
            pv += __shfl_xor_sync(0xffffffffu, pv, 4);
            pv += __shfl_xor_sync(0xffffffffu, pv, 2);
            pv += __shfl_xor_sync(0xffffffffu, pv, 1);
            if (l == 0) __stcg(&g_party[t & 1][cta], pv);

            if (t == STEPS - 1 && out_size >= STEPS + HIDDEN)
                out[STEPS + cta * ROWS + l] = hnew;

            __syncwarp();
            asm volatile("fence.acq_rel.gpu;" ::: "memory");   // producer release
            if (l == 0) __stcg(&g_tag[cta], base + (unsigned)t + 1u);
        }
    }

    // final readout ys[STEPS-1]
    if (cta == 0 && w == 0) {
        const unsigned int tgt = base + (unsigned)STEPS;
        const uint4* tp = (const uint4*)g_tag;
        for (;;) {
            uint4 v = ld_cg_v4_volatile(tp + l);
            bool ok = (v.x >= tgt) & (v.y >= tgt) & (v.z >= tgt) & (v.w >= tgt);
            if (__all_sync(0xffffffffu, ok)) break;
            __nanosleep(20);
        }
        asm volatile("" ::: "memory");
        const float* py = g_party[(STEPS - 1) & 1];
        float pv = __ldcg(py + l) + __ldcg(py + 32 + l)
                 + __ldcg(py + 64 + l) + __ldcg(py + 96 + l);
        pv += __shfl_xor_sync(0xffffffffu, pv, 16);
        pv += __shfl_xor_sync(0xffffffffu, pv, 8);
        pv += __shfl_xor_sync(0xffffffffu, pv, 4);
        pv += __shfl_xor_sync(0xffffffffu, pv, 2);
        pv += __shfl_xor_sync(0xffffffffu, pv, 1);
        if (l == 0) out[STEPS - 1] = bo + pv;
    }
}

extern "C" void kernel_launch(void* const* d_in, const int* in_sizes, int n_in,
                              void* d_out, int out_size)
{
    const float* inputs = (const float*)d_in[0];
    const float* W_ih   = (const float*)d_in[1];
    const float* W_hh   = (const float*)d_in[2];
    const float* b_ih   = (const float*)d_in[3];
    const float* b_hh   = (const float*)d_in[4];
    const float* W_out  = (const float*)d_in[5];
    const float* b_out  = (const float*)d_in[6];
    float* out = (float*)d_out;

    const int smem_bytes = (16 * KS * 16 * 32 + 8 * 512 + 2 * 32 * 8 + 8)
                           * (int)sizeof(float);
    cudaFuncSetAttribute(rnn_kernel,
                         cudaFuncAttributeMaxDynamicSharedMemorySize, smem_bytes);

    rnn_kernel<<<NCTA, NTH, smem_bytes>>>(
        inputs, W_ih, W_hh, b_ih, b_hh, W_out, b_out, out, out_size);
}